// round 16
// baseline (speedup 1.0000x reference)
#include <cuda_runtime.h>
#include <cuda_fp16.h>
#include <math.h>
#include <cstdint>

// x: [16, 64, 64, 512] -> rows M = 65536, C = 512
#define M_ROWS 65536
#define C_IN   512
#define D_DIM  64
#define V_DIM  256
#define BATCH  16
#define SEQ_Q  4096
#define SEQ_K  1024
#define NPROJ  384   // 64 theta | 64 phi | 256 g

// ---------------- scratch (device globals; no allocation allowed) ----------------
__device__ float   g_theta[M_ROWS * D_DIM];          // 16 MB (theta fp32, compact)
__device__ __half  g_xhi  [M_ROWS * C_IN];
__device__ __half  g_xlo  [M_ROWS * C_IN];
__device__ __half  g_thi  [M_ROWS * V_DIM];          // tmp, single fp16
__device__ __half  g_Bp_hi[NPROJ * C_IN];
__device__ __half  g_Bp_lo[NPROJ * C_IN];
__device__ __half  g_Bo_hi[C_IN * V_DIM];            // Wo, single fp16
__device__ __half  g_fhi  [BATCH * SEQ_K * D_DIM];
__device__ __half  g_flo  [BATCH * SEQ_K * D_DIM];
__device__ __half  g_gth  [BATCH * V_DIM * SEQ_K];   // g transposed, single fp16

// ================= baseline-ISA helpers =================
__device__ __forceinline__ uint32_t smem_u32(const void* p) {
    uint32_t a;
    asm("{ .reg .u64 t; cvta.to.shared.u64 t, %1; cvt.u32.u64 %0, t; }" : "=r"(a) : "l"(p));
    return a;
}
__device__ __forceinline__ float ex2f(float x) {
    float y; asm("ex2.approx.f32 %0, %1;" : "=f"(y) : "f"(x)); return y;
}
#define CP_ASYNC16(dst, src) \
    asm volatile("cp.async.cg.shared.global [%0], [%1], 16;" :: "r"(dst), "l"(src))
#define CP_COMMIT() asm volatile("cp.async.commit_group;" ::: "memory")
#define CP_WAIT(N)  asm volatile("cp.async.wait_group %0;" :: "n"(N) : "memory")
#define LDSM_X4(r0, r1, r2, r3, addr) \
    asm volatile("ldmatrix.sync.aligned.m8n8.x4.shared.b16 {%0,%1,%2,%3}, [%4];" \
                 : "=r"(r0), "=r"(r1), "=r"(r2), "=r"(r3) : "r"(addr))
// fp16 in, fp32 acc
#define MMA16816F(d, a, b0v, b1v) \
    asm volatile("mma.sync.aligned.m16n8k16.row.col.f32.f16.f16.f32 " \
                 "{%0,%1,%2,%3}, {%4,%5,%6,%7}, {%8,%9}, {%0,%1,%2,%3};" \
                 : "+f"((d)[0]), "+f"((d)[1]), "+f"((d)[2]), "+f"((d)[3]) \
                 : "r"((a)[0]), "r"((a)[1]), "r"((a)[2]), "r"((a)[3]), \
                   "r"(b0v), "r"(b1v))
// fp16 in, fp16 acc (dense-GEMM correction terms)
#define MMA16816H(d, a, b0v, b1v) \
    asm volatile("mma.sync.aligned.m16n8k16.row.col.f16.f16.f16.f16 " \
                 "{%0,%1}, {%2,%3,%4,%5}, {%6,%7}, {%0,%1};" \
                 : "+r"((d)[0]), "+r"((d)[1]) \
                 : "r"((a)[0]), "r"((a)[1]), "r"((a)[2]), "r"((a)[3]), \
                   "r"(b0v), "r"(b1v))

// ================= conversion / packing (fp16 hi/lo) =================
__global__ void convert_x_k(const float* __restrict__ x,
                            __half* __restrict__ xhi, __half* __restrict__ xlo)
{
    size_t i = ((size_t)blockIdx.x * blockDim.x + threadIdx.x) * 8;
    if (i >= (size_t)M_ROWS * C_IN) return;
    float4 a = *(const float4*)(x + i);
    float4 b = *(const float4*)(x + i + 4);
    float v[8] = {a.x, a.y, a.z, a.w, b.x, b.y, b.z, b.w};
    __half h[8], l[8];
    #pragma unroll
    for (int j = 0; j < 8; j++) {
        h[j] = __float2half(v[j]);
        l[j] = __float2half(v[j] - __half2float(h[j]));
    }
    *(uint4*)(xhi + i) = *(const uint4*)h;
    *(uint4*)(xlo + i) = *(const uint4*)l;
}

__global__ void pack_proj_k(const float* __restrict__ Wt, const float* __restrict__ Wp,
                            const float* __restrict__ Wg,
                            __half* __restrict__ bhi, __half* __restrict__ blo)
{
    int i = blockIdx.x * blockDim.x + threadIdx.x;
    if (i >= NPROJ * C_IN) return;
    int n = i / C_IN, k = i % C_IN;
    float v;
    if (n < 64)       v = Wt[k * 64 + n];
    else if (n < 128) v = Wp[k * 64 + (n - 64)];
    else              v = Wg[k * 256 + (n - 128)];
    __half h = __float2half(v);
    bhi[i] = h;
    blo[i] = __float2half(v - __half2float(h));
}

__global__ void pack_wo_k(const float* __restrict__ Wo, __half* __restrict__ bhi)
{
    int i = blockIdx.x * blockDim.x + threadIdx.x;
    if (i >= C_IN * V_DIM) return;
    int n = i / V_DIM, k = i % V_DIM;
    bhi[i] = __float2half(Wo[k * C_IN + n]);
}

// ================= fp16 GEMM: 128x128x32, 3-stage, warp 64x32 =================
// TERMS=3: AhBh[f32] + AlBh[f16] + AhBl[f16].  TERMS=1: AhBh[f32] only.
// EPI=0: normal C write (+ optional gamma*acc + res residual)      [Wo]
// EPI=1: theta compact fp32 (cols 0-63) + phi 2x2-pool fp16 hi/lo  [proj block0]
// EPI=2: g 2x2-pool + transpose -> gth single fp16                  [proj blocks1-2]
#define BK      32
#define ASTRIDE 40
#define STAGES  3
#define G_AR    (128 * ASTRIDE * 2)
#define G_STAGE (4 * G_AR)
#define GEMM_SMEM_BYTES (STAGES * G_STAGE)

template <int KB, int TERMS, int EPI>
__global__ __launch_bounds__(256, 1) void gemm_mma(
    const __half* __restrict__ Ahi, const __half* __restrict__ Alo,
    const __half* __restrict__ Bhi, const __half* __restrict__ Blo,
    float* __restrict__ C, int ldc, int n_base,
    const float* __restrict__ res, const float* __restrict__ gammaP,
    float* __restrict__ thC, __half* __restrict__ e1, __half* __restrict__ e2)
{
    extern __shared__ __half sg[];
    const uint32_t sbase = smem_u32(sg);

    const int tid  = threadIdx.x;
    const int lane = tid & 31;
    const int wid  = tid >> 5;
    const int warpM = wid >> 2;
    const int warpN = wid & 3;
    const int m0 = blockIdx.y * 128;
    const int n0 = n_base + blockIdx.x * 128;

    constexpr int CHUNKS = KB / BK;

    auto load_chunk = [&](int c, int stg) {
        const int kcol = c * BK;
        const uint32_t base = sbase + stg * G_STAGE;
        if (TERMS == 3) {
            #pragma unroll
            for (int it = 0; it < 8; it++) {
                int idx = tid + it * 256;
                int arr = idx >> 9;
                int j = idx & 511;
                int row = j >> 2, c16 = j & 3;
                const __half* src =
                    (arr == 0) ? Ahi + (size_t)(m0 + row) * KB + kcol + c16 * 8 :
                    (arr == 1) ? Alo + (size_t)(m0 + row) * KB + kcol + c16 * 8 :
                    (arr == 2) ? Bhi + (size_t)(n0 + row) * KB + kcol + c16 * 8 :
                                 Blo + (size_t)(n0 + row) * KB + kcol + c16 * 8;
                CP_ASYNC16(base + arr * G_AR + (row * ASTRIDE + c16 * 8) * 2, src);
            }
        } else {
            #pragma unroll
            for (int it = 0; it < 4; it++) {
                int idx = tid + it * 256;
                int half_ = idx >> 9;
                int j = idx & 511;
                int row = j >> 2, c16 = j & 3;
                const __half* src = half_
                    ? Bhi + (size_t)(n0 + row) * KB + kcol + c16 * 8
                    : Ahi + (size_t)(m0 + row) * KB + kcol + c16 * 8;
                CP_ASYNC16(base + (half_ ? 2 : 0) * G_AR + (row * ASTRIDE + c16 * 8) * 2, src);
            }
        }
        CP_COMMIT();
    };

    float    accF[4][4][4];
    uint32_t accA[4][4][2];
    uint32_t accB[4][4][2];
    #pragma unroll
    for (int i = 0; i < 4; i++)
        #pragma unroll
        for (int j = 0; j < 4; j++) {
            #pragma unroll
            for (int r = 0; r < 4; r++) accF[i][j][r] = 0.f;
            accA[i][j][0] = accA[i][j][1] = 0u;
            accB[i][j][0] = accB[i][j][1] = 0u;
        }

    #pragma unroll
    for (int s = 0; s < STAGES - 1; s++) load_chunk(s, s);

    for (int c = 0; c < CHUNKS; c++) {
        CP_WAIT(STAGES - 2);
        __syncthreads();

        const uint32_t base = sbase + (c % STAGES) * G_STAGE;
        const uint32_t ahB = base, alB = base + G_AR, bhB = base + 2 * G_AR, blB = base + 3 * G_AR;
        #pragma unroll
        for (int k0 = 0; k0 < BK; k0 += 16) {
            uint32_t ah[4][4], al[4][4];
            uint32_t colA = k0 + (lane >> 4) * 8;
            #pragma unroll
            for (int i = 0; i < 4; i++) {
                uint32_t roff = ((warpM * 64 + i * 16 + (lane & 15)) * ASTRIDE + colA) * 2;
                LDSM_X4(ah[i][0], ah[i][1], ah[i][2], ah[i][3], ahB + roff);
                if (TERMS == 3)
                    LDSM_X4(al[i][0], al[i][1], al[i][2], al[i][3], alB + roff);
            }
            uint32_t bh[2][4], bl[2][4];
            int g = lane >> 3, rr = lane & 7;
            #pragma unroll
            for (int j2 = 0; j2 < 2; j2++) {
                uint32_t roff = ((warpN * 32 + j2 * 16 + (g & 2) * 4 + rr) * ASTRIDE
                                 + k0 + (g & 1) * 8) * 2;
                LDSM_X4(bh[j2][0], bh[j2][1], bh[j2][2], bh[j2][3], bhB + roff);
                if (TERMS == 3)
                    LDSM_X4(bl[j2][0], bl[j2][1], bl[j2][2], bl[j2][3], blB + roff);
            }
            #pragma unroll
            for (int i = 0; i < 4; i++)
                #pragma unroll
                for (int j = 0; j < 4; j++) {
                    uint32_t b0h = bh[j >> 1][(j & 1) * 2], b1h = bh[j >> 1][(j & 1) * 2 + 1];
                    MMA16816F(accF[i][j], ah[i], b0h, b1h);
                    if (TERMS == 3) {
                        uint32_t b0l = bl[j >> 1][(j & 1) * 2], b1l = bl[j >> 1][(j & 1) * 2 + 1];
                        MMA16816H(accA[i][j], al[i], b0h, b1h);
                        MMA16816H(accB[i][j], ah[i], b0l, b1l);
                    }
                }
        }
        if (c + STAGES - 1 < CHUNKS) load_chunk(c + STAGES - 1, (c + STAGES - 1) % STAGES);
        else CP_COMMIT();
    }

    // ---- finalize per-thread tile values t[i][j][4] ----
    float tv[4][4][4];
    #pragma unroll
    for (int i = 0; i < 4; i++)
        #pragma unroll
        for (int j = 0; j < 4; j++) {
            tv[i][j][0] = accF[i][j][0]; tv[i][j][1] = accF[i][j][1];
            tv[i][j][2] = accF[i][j][2]; tv[i][j][3] = accF[i][j][3];
            if (TERMS == 3) {
                float2 a01 = __half22float2(*(__half2*)&accA[i][j][0]);
                float2 a23 = __half22float2(*(__half2*)&accA[i][j][1]);
                float2 b01 = __half22float2(*(__half2*)&accB[i][j][0]);
                float2 b23 = __half22float2(*(__half2*)&accB[i][j][1]);
                tv[i][j][0] += a01.x + b01.x; tv[i][j][1] += a01.y + b01.y;
                tv[i][j][2] += a23.x + b23.x; tv[i][j][3] += a23.y + b23.y;
            }
        }

    if (EPI == 0) {
        const float gamma = res ? *gammaP : 0.f;
        #pragma unroll
        for (int i = 0; i < 4; i++)
            #pragma unroll
            for (int j = 0; j < 4; j++) {
                int gr = m0 + warpM * 64 + i * 16 + (lane >> 2);
                int gc = n0 + warpN * 32 + j * 8 + (lane & 3) * 2;
                size_t off0 = (size_t)gr * ldc + gc;
                size_t off1 = off0 + (size_t)8 * ldc;
                if (res) {
                    float2 r0 = *(const float2*)(res + off0);
                    float2 r1 = *(const float2*)(res + off1);
                    *(float2*)(C + off0) = make_float2(fmaf(gamma, tv[i][j][0], r0.x),
                                                       fmaf(gamma, tv[i][j][1], r0.y));
                    *(float2*)(C + off1) = make_float2(fmaf(gamma, tv[i][j][2], r1.x),
                                                       fmaf(gamma, tv[i][j][3], r1.y));
                } else {
                    *(float2*)(C + off0) = make_float2(tv[i][j][0], tv[i][j][1]);
                    *(float2*)(C + off1) = make_float2(tv[i][j][2], tv[i][j][3]);
                }
            }
    } else if (EPI == 1) {
        // theta (cols 0-63, warpN 0-1): compact fp32 write
        if (warpN < 2) {
            #pragma unroll
            for (int i = 0; i < 4; i++)
                #pragma unroll
                for (int j = 0; j < 4; j++) {
                    int gr = m0 + warpM * 64 + i * 16 + (lane >> 2);
                    int gc = warpN * 32 + j * 8 + (lane & 3) * 2;
                    *(float2*)(thC + (size_t)gr * 64 + gc) = make_float2(tv[i][j][0], tv[i][j][1]);
                    *(float2*)(thC + (size_t)(gr + 8) * 64 + gc) = make_float2(tv[i][j][2], tv[i][j][3]);
                }
        }
        // phi (cols 64-127, warpN 2-3): stage to smem, 2x2 pool, fp16 hi/lo
        __syncthreads();                       // compute reads of smem done
        float* smf = (float*)sg;               // [128][68]
        if (warpN >= 2) {
            #pragma unroll
            for (int i = 0; i < 4; i++)
                #pragma unroll
                for (int j = 0; j < 4; j++) {
                    int lr = warpM * 64 + i * 16 + (lane >> 2);
                    int cc = (warpN - 2) * 32 + j * 8 + (lane & 3) * 2;
                    smf[lr * 68 + cc]           = tv[i][j][0];
                    smf[lr * 68 + cc + 1]       = tv[i][j][1];
                    smf[(lr + 8) * 68 + cc]     = tv[i][j][2];
                    smf[(lr + 8) * 68 + cc + 1] = tv[i][j][3];
                }
        }
        __syncthreads();
        {
            int bb = m0 >> 12, ii = (m0 & 4095) >> 7;
            int cc = tid & 63;
            #pragma unroll
            for (int s = 0; s < 8; s++) {
                int jj = (tid >> 6) * 8 + s;
                float p = fmaxf(fmaxf(smf[(jj * 2) * 68 + cc],      smf[(jj * 2 + 1) * 68 + cc]),
                                fmaxf(smf[(jj * 2 + 64) * 68 + cc], smf[(jj * 2 + 65) * 68 + cc]));
                __half h = __float2half(p);
                __half lo = __float2half(p - __half2float(h));
                size_t off = (size_t)(bb * 1024 + ii * 32 + jj) * 64 + cc;
                e1[off] = h;
                e2[off] = lo;
            }
        }
    } else {  // EPI == 2: g pool + transpose -> gth
        __syncthreads();
        float* smf = (float*)sg;               // [128][132]
        #pragma unroll
        for (int i = 0; i < 4; i++)
            #pragma unroll
            for (int j = 0; j < 4; j++) {
                int lr = warpM * 64 + i * 16 + (lane >> 2);
                int cc = warpN * 32 + j * 8 + (lane & 3) * 2;
                smf[lr * 132 + cc]           = tv[i][j][0];
                smf[lr * 132 + cc + 1]       = tv[i][j][1];
                smf[(lr + 8) * 132 + cc]     = tv[i][j][2];
                smf[(lr + 8) * 132 + cc + 1] = tv[i][j][3];
            }
        __syncthreads();
        {
            int bb = m0 >> 12, ii = (m0 & 4095) >> 7;
            int vloc = tid >> 1;               // 0..127
            int kh = (tid & 1) * 16;
            int vglob = (n0 - 128) + vloc;
            __half hv[16];
            #pragma unroll
            for (int s = 0; s < 16; s++) {
                int jj = kh + s;
                float p = fmaxf(fmaxf(smf[(jj * 2) * 132 + vloc],      smf[(jj * 2 + 1) * 132 + vloc]),
                                fmaxf(smf[(jj * 2 + 64) * 132 + vloc], smf[(jj * 2 + 65) * 132 + vloc]));
                hv[s] = __float2half(p);
            }
            size_t off = (size_t)(bb * 256 + vglob) * 1024 + ii * 32 + kh;
            *(uint4*)(e1 + off)     = *(const uint4*)hv;
            *(uint4*)(e1 + off + 8) = *(const uint4*)(hv + 8);
        }
    }
}

// ================= flash attention (fp16; P, g, tmp single-precision fp16) ===========
#define OFF_TH  0u                 // theta hi [128][72]
#define OFF_TL  9216u              // theta lo
#define OFF_FB(buf) (18432u + (buf) * 9216u)   // phi buf: hi [64][72] then lo
#define OFF_GH  36864u             // gT fp16 [256][72]
#define OFF_SP  55296u             // P fp16 [128][72]
#define ATTN_H_ELEMS 64512u
#define ATTN_SMEM_BYTES (64512 * 2 + 2 * 512 * 4)   // 133120

__global__ __launch_bounds__(512, 1) void attn_k(
    const float* __restrict__ theta,
    const __half* __restrict__ fhi, const __half* __restrict__ flo,
    const __half* __restrict__ gth,
    __half* __restrict__ thi)
{
    extern __shared__ __half sb[];
    float* redA = (float*)(sb + ATTN_H_ELEMS);
    float* redB = redA + 512;

    const uint32_t sb32 = smem_u32(sb);
    const int tid  = threadIdx.x;
    const int lane = tid & 31;
    const int wid  = tid >> 5;
    const int warpM = wid >> 2;
    const int warpN = wid & 3;
    const int b  = blockIdx.y;
    const int qt = blockIdx.x;
    const int qbase = b * SEQ_Q + qt * 128;
    const float L2E = 1.4426950408889634f;

    auto issue_phi = [&](int kt, int buf) {
        const size_t fb = (size_t)(b * SEQ_K + kt * 64) * 64;
        const uint32_t fB = OFF_FB(buf);
        #pragma unroll
        for (int i = 0; i < 2; i++) {
            int id = tid + i * 512;
            int half_ = id >> 9, j = id & 511;
            int row = j >> 3, c = j & 7;
            CP_ASYNC16(sb32 + (fB + half_ * 4608u + row * 72 + c * 8) * 2,
                       (half_ ? flo : fhi) + fb + (size_t)row * 64 + c * 8);
        }
        CP_COMMIT();
    };
    issue_phi(0, 0);

    // theta (scaled by log2e) -> smem fp16 hi/lo  (compact [M][64] fp32 source)
    #pragma unroll
    for (int i = tid; i < 128 * 16; i += 512) {
        int q = i >> 4, c4 = i & 15;
        float4 v = *(const float4*)(theta + (size_t)(qbase + q) * 64 + c4 * 4);
        float f[4] = {v.x * L2E, v.y * L2E, v.z * L2E, v.w * L2E};
        __half h[4], l[4];
        #pragma unroll
        for (int j = 0; j < 4; j++) {
            h[j] = __float2half(f[j]);
            l[j] = __float2half(f[j] - __half2float(h[j]));
        }
        uint32_t o = q * 72 + c4 * 4;
        *(uint2*)(sb + OFF_TH + o) = *(const uint2*)h;
        *(uint2*)(sb + OFF_TL + o) = *(const uint2*)l;
    }

    float acc[2][8][4];
    float m[2][2], l[2][2];
    #pragma unroll
    for (int mf = 0; mf < 2; mf++) {
        m[mf][0] = -1e30f; m[mf][1] = -1e30f;
        l[mf][0] = 0.f;    l[mf][1] = 0.f;
        #pragma unroll
        for (int nf = 0; nf < 8; nf++)
            #pragma unroll
            for (int c = 0; c < 4; c++) acc[mf][nf][c] = 0.f;
    }

    const int rowA = warpM * 32 + (lane & 15);
    const int rq   = lane >> 2;
    const int cq2  = (lane & 3) * 2;

    for (int kt = 0; kt < 16; kt++) {
        const int buf = kt & 1;
        __syncthreads();
        {
            const size_t gb = (size_t)b * V_DIM * SEQ_K + kt * 64;
            #pragma unroll
            for (int i = 0; i < 4; i++) {
                int id = tid + i * 512;
                int v = id >> 3, c = id & 7;
                CP_ASYNC16(sb32 + (OFF_GH + v * 72 + c * 8) * 2,
                           gth + gb + (size_t)v * SEQ_K + c * 8);
            }
            CP_COMMIT();
        }
        CP_WAIT(1);
        __syncthreads();

        // ---- QK: 3-term, all f32-acc ----
        const uint32_t fH = OFF_FB(buf), fL = fH + 4608u;
        float aq[2][2][4];
        #pragma unroll
        for (int mf = 0; mf < 2; mf++)
            #pragma unroll
            for (int nf = 0; nf < 2; nf++)
                #pragma unroll
                for (int c = 0; c < 4; c++) aq[mf][nf][c] = 0.f;

        #pragma unroll
        for (int k0 = 0; k0 < 64; k0 += 16) {
            uint32_t th0[4], th1[4], tl0[4], tl1[4], fh[4], fl[4];
            uint32_t colA = k0 + (lane >> 4) * 8;
            LDSM_X4(th0[0], th0[1], th0[2], th0[3], sb32 + (OFF_TH + (rowA) * 72 + colA) * 2);
            LDSM_X4(th1[0], th1[1], th1[2], th1[3], sb32 + (OFF_TH + (rowA + 16) * 72 + colA) * 2);
            LDSM_X4(tl0[0], tl0[1], tl0[2], tl0[3], sb32 + (OFF_TL + (rowA) * 72 + colA) * 2);
            LDSM_X4(tl1[0], tl1[1], tl1[2], tl1[3], sb32 + (OFF_TL + (rowA + 16) * 72 + colA) * 2);
            int g = lane >> 3, rr = lane & 7;
            uint32_t brow = (warpN * 16 + (g & 2) * 4 + rr) * 72 + k0 + (g & 1) * 8;
            LDSM_X4(fh[0], fh[1], fh[2], fh[3], sb32 + (fH + brow) * 2);
            LDSM_X4(fl[0], fl[1], fl[2], fl[3], sb32 + (fL + brow) * 2);
            MMA16816F(aq[0][0], th0, fh[0], fh[1]);
            MMA16816F(aq[0][1], th0, fh[2], fh[3]);
            MMA16816F(aq[1][0], th1, fh[0], fh[1]);
            MMA16816F(aq[1][1], th1, fh[2], fh[3]);
            MMA16816F(aq[0][0], tl0, fh[0], fh[1]);
            MMA16816F(aq[0][1], tl0, fh[2], fh[3]);
            MMA16816F(aq[1][0], tl1, fh[0], fh[1]);
            MMA16816F(aq[1][1], tl1, fh[2], fh[3]);
            MMA16816F(aq[0][0], th0, fl[0], fl[1]);
            MMA16816F(aq[0][1], th0, fl[2], fl[3]);
            MMA16816F(aq[1][0], th1, fl[0], fl[1]);
            MMA16816F(aq[1][1], th1, fl[2], fl[3]);
        }

        if (kt + 1 < 16) issue_phi(kt + 1, buf ^ 1);

        // ---- online softmax ----
        float mx[2][2];
        #pragma unroll
        for (int mf = 0; mf < 2; mf++)
            #pragma unroll
            for (int h = 0; h < 2; h++) {
                float t = fmaxf(fmaxf(aq[mf][0][h * 2], aq[mf][0][h * 2 + 1]),
                                fmaxf(aq[mf][1][h * 2], aq[mf][1][h * 2 + 1]));
                t = fmaxf(t, __shfl_xor_sync(0xffffffffu, t, 1));
                t = fmaxf(t, __shfl_xor_sync(0xffffffffu, t, 2));
                mx[mf][h] = t;
            }
        if ((lane & 3) == 0) {
            #pragma unroll
            for (int mf = 0; mf < 2; mf++)
                #pragma unroll
                for (int h = 0; h < 2; h++)
                    redA[warpN * 128 + warpM * 32 + mf * 16 + h * 8 + rq] = mx[mf][h];
        }
        __syncthreads();

        float mnew[2][2], scale[2][2], rsum[2][2];
        #pragma unroll
        for (int mf = 0; mf < 2; mf++)
            #pragma unroll
            for (int h = 0; h < 2; h++) {
                int r = warpM * 32 + mf * 16 + h * 8 + rq;
                float v = m[mf][h];
                #pragma unroll
                for (int w = 0; w < 4; w++) v = fmaxf(v, redA[w * 128 + r]);
                mnew[mf][h] = v;
                rsum[mf][h] = 0.f;
            }

        #pragma unroll
        for (int mf = 0; mf < 2; mf++)
            #pragma unroll
            for (int nf = 0; nf < 2; nf++)
                #pragma unroll
                for (int h = 0; h < 2; h++) {
                    float p0 = ex2f(aq[mf][nf][h * 2]     - mnew[mf][h]);
                    float p1 = ex2f(aq[mf][nf][h * 2 + 1] - mnew[mf][h]);
                    rsum[mf][h] += p0 + p1;
                    int row = warpM * 32 + mf * 16 + h * 8 + rq;
                    int col = warpN * 16 + nf * 8 + cq2;
                    *(__half2*)(sb + OFF_SP + row * 72 + col) = __floats2half2_rn(p0, p1);
                }
        #pragma unroll
        for (int mf = 0; mf < 2; mf++)
            #pragma unroll
            for (int h = 0; h < 2; h++) {
                float t = rsum[mf][h];
                t += __shfl_xor_sync(0xffffffffu, t, 1);
                t += __shfl_xor_sync(0xffffffffu, t, 2);
                rsum[mf][h] = t;
                scale[mf][h] = ex2f(m[mf][h] - mnew[mf][h]);
                m[mf][h] = mnew[mf][h];
            }
        if ((lane & 3) == 0) {
            #pragma unroll
            for (int mf = 0; mf < 2; mf++)
                #pragma unroll
                for (int h = 0; h < 2; h++)
                    redB[warpN * 128 + warpM * 32 + mf * 16 + h * 8 + rq] = rsum[mf][h];
        }
        if (kt + 1 < 16) { CP_WAIT(1); }
        else             { CP_WAIT(0); }
        __syncthreads();

        #pragma unroll
        for (int mf = 0; mf < 2; mf++)
            #pragma unroll
            for (int h = 0; h < 2; h++) {
                int r = warpM * 32 + mf * 16 + h * 8 + rq;
                float s = 0.f;
                #pragma unroll
                for (int w = 0; w < 4; w++) s += redB[w * 128 + r];
                l[mf][h] = l[mf][h] * scale[mf][h] + s;
            }
        #pragma unroll
        for (int mf = 0; mf < 2; mf++)
            #pragma unroll
            for (int nf = 0; nf < 8; nf++) {
                acc[mf][nf][0] *= scale[mf][0];
                acc[mf][nf][1] *= scale[mf][0];
                acc[mf][nf][2] *= scale[mf][1];
                acc[mf][nf][3] *= scale[mf][1];
            }

        // ---- PV: 1-term f32-acc (P x g) ----
        #pragma unroll
        for (int k0 = 0; k0 < 64; k0 += 16) {
            uint32_t ph0[4], ph1[4];
            uint32_t colA = k0 + (lane >> 4) * 8;
            LDSM_X4(ph0[0], ph0[1], ph0[2], ph0[3], sb32 + (OFF_SP + (rowA) * 72 + colA) * 2);
            LDSM_X4(ph1[0], ph1[1], ph1[2], ph1[3], sb32 + (OFF_SP + (rowA + 16) * 72 + colA) * 2);
            int g = lane >> 3, rr = lane & 7;
            #pragma unroll
            for (int j2 = 0; j2 < 4; j2++) {
                uint32_t gh[4];
                uint32_t brow = (warpN * 64 + j2 * 16 + (g & 2) * 4 + rr) * 72 + k0 + (g & 1) * 8;
                LDSM_X4(gh[0], gh[1], gh[2], gh[3], sb32 + (OFF_GH + brow) * 2);
                MMA16816F(acc[0][j2 * 2 + 0], ph0, gh[0], gh[1]);
                MMA16816F(acc[0][j2 * 2 + 1], ph0, gh[2], gh[3]);
                MMA16816F(acc[1][j2 * 2 + 0], ph1, gh[0], gh[1]);
                MMA16816F(acc[1][j2 * 2 + 1], ph1, gh[2], gh[3]);
            }
        }
    }

    // epilogue: tmp = acc / l -> single fp16
    #pragma unroll
    for (int mf = 0; mf < 2; mf++)
        #pragma unroll
        for (int h = 0; h < 2; h++) {
            float inv = 1.f / l[mf][h];
            int row = qbase + warpM * 32 + mf * 16 + h * 8 + rq;
            #pragma unroll
            for (int nf = 0; nf < 8; nf++) {
                int col = warpN * 64 + nf * 8 + cq2;
                float v0 = acc[mf][nf][h * 2]     * inv;
                float v1 = acc[mf][nf][h * 2 + 1] * inv;
                *(__half2*)(thi + (size_t)row * V_DIM + col) = __floats2half2_rn(v0, v1);
            }
        }
}

// ---------------- launch ----------------
extern "C" void kernel_launch(void* const* d_in, const int* in_sizes, int n_in,
                              void* d_out, int out_size)
{
    const float* x     = (const float*)d_in[0];
    const float* Wt    = (const float*)d_in[1];
    const float* Wp    = (const float*)d_in[2];
    const float* Wg    = (const float*)d_in[3];
    const float* Wo    = (const float*)d_in[4];
    const float* gamma = (const float*)d_in[5];
    float* out = (float*)d_out;

    float *theta;
    __half *xhi, *xlo, *thi, *Bph, *Bpl, *Boh, *fhi, *flo, *gth;
    cudaGetSymbolAddress((void**)&theta, g_theta);
    cudaGetSymbolAddress((void**)&xhi,  g_xhi);
    cudaGetSymbolAddress((void**)&xlo,  g_xlo);
    cudaGetSymbolAddress((void**)&thi,  g_thi);
    cudaGetSymbolAddress((void**)&Bph,  g_Bp_hi);
    cudaGetSymbolAddress((void**)&Bpl,  g_Bp_lo);
    cudaGetSymbolAddress((void**)&Boh,  g_Bo_hi);
    cudaGetSymbolAddress((void**)&fhi,  g_fhi);
    cudaGetSymbolAddress((void**)&flo,  g_flo);
    cudaGetSymbolAddress((void**)&gth,  g_gth);

    cudaFuncSetAttribute((const void*)gemm_mma<512, 3, 1>, cudaFuncAttributeMaxDynamicSharedMemorySize, GEMM_SMEM_BYTES);
    cudaFuncSetAttribute((const void*)gemm_mma<512, 1, 2>, cudaFuncAttributeMaxDynamicSharedMemorySize, GEMM_SMEM_BYTES);
    cudaFuncSetAttribute((const void*)gemm_mma<256, 1, 0>, cudaFuncAttributeMaxDynamicSharedMemorySize, GEMM_SMEM_BYTES);
    cudaFuncSetAttribute(attn_k, cudaFuncAttributeMaxDynamicSharedMemorySize, ATTN_SMEM_BYTES);

    convert_x_k<<<(M_ROWS * C_IN / 8 + 255) / 256, 256>>>(x, xhi, xlo);
    pack_proj_k<<<(NPROJ * C_IN + 255) / 256, 256>>>(Wt, Wp, Wg, Bph, Bpl);
    pack_wo_k<<<(C_IN * V_DIM + 255) / 256, 256>>>(Wo, Boh);
    // proj block 0 (theta|phi): 3-term; epilogue emits compact theta + pooled phi hi/lo
    gemm_mma<512, 3, 1><<<dim3(1, M_ROWS / 128), 256, GEMM_SMEM_BYTES>>>(
        xhi, xlo, Bph, Bpl, nullptr, 0, 0, nullptr, nullptr, theta, fhi, flo);
    // proj blocks 1-2 (g): 1-term; epilogue pools + transposes -> gth fp16
    gemm_mma<512, 1, 2><<<dim3(2, M_ROWS / 128), 256, GEMM_SMEM_BYTES>>>(
        xhi, xlo, Bph, Bpl, nullptr, 0, 128, nullptr, nullptr, nullptr, gth, nullptr);
    // flash attention
    attn_k<<<dim3(SEQ_Q / 128, BATCH), 512, ATTN_SMEM_BYTES>>>(
        theta, fhi, flo, gth, thi);
    // Wo projection (1-term) + residual: out = gamma * (tmp @ Wo) + x
    gemm_mma<256, 1, 0><<<dim3(C_IN / 128, M_ROWS / 128), 256, GEMM_SMEM_BYTES>>>(
        thi, nullptr, Boh, nullptr, out, C_IN, 0, x, gamma, nullptr, nullptr, nullptr);
}

// round 17
// speedup vs baseline: 1.3992x; 1.3992x over previous
#include <cuda_runtime.h>
#include <cuda_fp16.h>
#include <math.h>
#include <cstdint>

// x: [16, 64, 64, 512] -> rows M = 65536, C = 512
#define M_ROWS 65536
#define C_IN   512
#define D_DIM  64
#define V_DIM  256
#define BATCH  16
#define SEQ_Q  4096
#define SEQ_K  1024
#define NPROJ  384   // 64 theta | 64 phi | 256 g

// ---------------- scratch (device globals; no allocation allowed) ----------------
__device__ float   g_thph [M_ROWS * 128];            // theta|phi fp32 compact (32 MB)
__device__ __half  g_gh   [M_ROWS * V_DIM];          // unpooled g fp16 (32 MB)
__device__ __half  g_xhi  [M_ROWS * C_IN];
__device__ __half  g_xlo  [M_ROWS * C_IN];
__device__ __half  g_thi  [M_ROWS * V_DIM];          // tmp fp16
__device__ __half  g_Bp_hi[NPROJ * C_IN];
__device__ __half  g_Bp_lo[NPROJ * C_IN];
__device__ __half  g_Bo_hi[C_IN * V_DIM];
__device__ __half  g_fhi  [BATCH * SEQ_K * D_DIM];
__device__ __half  g_flo  [BATCH * SEQ_K * D_DIM];
__device__ __half  g_gth  [BATCH * V_DIM * SEQ_K];   // g pooled+transposed fp16

// ================= baseline-ISA helpers =================
__device__ __forceinline__ uint32_t smem_u32(const void* p) {
    uint32_t a;
    asm("{ .reg .u64 t; cvta.to.shared.u64 t, %1; cvt.u32.u64 %0, t; }" : "=r"(a) : "l"(p));
    return a;
}
__device__ __forceinline__ float ex2f(float x) {
    float y; asm("ex2.approx.f32 %0, %1;" : "=f"(y) : "f"(x)); return y;
}
#define CP_ASYNC16(dst, src) \
    asm volatile("cp.async.cg.shared.global [%0], [%1], 16;" :: "r"(dst), "l"(src))
#define CP_COMMIT() asm volatile("cp.async.commit_group;" ::: "memory")
#define CP_WAIT(N)  asm volatile("cp.async.wait_group %0;" :: "n"(N) : "memory")
#define LDSM_X4(r0, r1, r2, r3, addr) \
    asm volatile("ldmatrix.sync.aligned.m8n8.x4.shared.b16 {%0,%1,%2,%3}, [%4];" \
                 : "=r"(r0), "=r"(r1), "=r"(r2), "=r"(r3) : "r"(addr))
// fp16 in, fp32 acc
#define MMA16816F(d, a, b0v, b1v) \
    asm volatile("mma.sync.aligned.m16n8k16.row.col.f32.f16.f16.f32 " \
                 "{%0,%1,%2,%3}, {%4,%5,%6,%7}, {%8,%9}, {%0,%1,%2,%3};" \
                 : "+f"((d)[0]), "+f"((d)[1]), "+f"((d)[2]), "+f"((d)[3]) \
                 : "r"((a)[0]), "r"((a)[1]), "r"((a)[2]), "r"((a)[3]), \
                   "r"(b0v), "r"(b1v))
// fp16 in, fp16 acc (split-precision correction terms)
#define MMA16816H(d, a, b0v, b1v) \
    asm volatile("mma.sync.aligned.m16n8k16.row.col.f16.f16.f16.f16 " \
                 "{%0,%1}, {%2,%3,%4,%5}, {%6,%7}, {%0,%1};" \
                 : "+r"((d)[0]), "+r"((d)[1]) \
                 : "r"((a)[0]), "r"((a)[1]), "r"((a)[2]), "r"((a)[3]), \
                   "r"(b0v), "r"(b1v))

// ================= conversion / packing (fp16 hi/lo) =================
__global__ void convert_x_k(const float* __restrict__ x,
                            __half* __restrict__ xhi, __half* __restrict__ xlo)
{
    size_t i = ((size_t)blockIdx.x * blockDim.x + threadIdx.x) * 8;
    if (i >= (size_t)M_ROWS * C_IN) return;
    float4 a = *(const float4*)(x + i);
    float4 b = *(const float4*)(x + i + 4);
    float v[8] = {a.x, a.y, a.z, a.w, b.x, b.y, b.z, b.w};
    __half h[8], l[8];
    #pragma unroll
    for (int j = 0; j < 8; j++) {
        h[j] = __float2half(v[j]);
        l[j] = __float2half(v[j] - __half2float(h[j]));
    }
    *(uint4*)(xhi + i) = *(const uint4*)h;
    *(uint4*)(xlo + i) = *(const uint4*)l;
}

__global__ void pack_proj_k(const float* __restrict__ Wt, const float* __restrict__ Wp,
                            const float* __restrict__ Wg,
                            __half* __restrict__ bhi, __half* __restrict__ blo)
{
    int i = blockIdx.x * blockDim.x + threadIdx.x;
    if (i >= NPROJ * C_IN) return;
    int n = i / C_IN, k = i % C_IN;
    float v;
    if (n < 64)       v = Wt[k * 64 + n];
    else if (n < 128) v = Wp[k * 64 + (n - 64)];
    else              v = Wg[k * 256 + (n - 128)];
    __half h = __float2half(v);
    bhi[i] = h;
    blo[i] = __float2half(v - __half2float(h));
}

__global__ void pack_wo_k(const float* __restrict__ Wo, __half* __restrict__ bhi)
{
    int i = blockIdx.x * blockDim.x + threadIdx.x;
    if (i >= C_IN * V_DIM) return;
    int n = i / V_DIM, k = i % V_DIM;
    bhi[i] = __float2half(Wo[k * C_IN + n]);
}

// ================= fp16 GEMM: 128x128x32, 3-stage, warp 64x32 =================
// TERMS=3: AhBh[f32] + AlBh[f16] + AhBl[f16].  TERMS=1: AhBh[f32] only.
// OUTH=0: fp32 C write (+ optional gamma*acc + res residual)
// OUTH=1: fp16 Ch write (plain)
#define BK      32
#define ASTRIDE 40
#define STAGES  3
#define G_AR    (128 * ASTRIDE * 2)
#define G_STAGE (4 * G_AR)
#define GEMM_SMEM_BYTES (STAGES * G_STAGE)

template <int KB, int TERMS, int OUTH>
__global__ __launch_bounds__(256, 1) void gemm_mma(
    const __half* __restrict__ Ahi, const __half* __restrict__ Alo,
    const __half* __restrict__ Bhi, const __half* __restrict__ Blo,
    float* __restrict__ C, __half* __restrict__ Ch, int ldc, int n_base,
    const float* __restrict__ res, const float* __restrict__ gammaP)
{
    extern __shared__ __half sg[];
    const uint32_t sbase = smem_u32(sg);

    const int tid  = threadIdx.x;
    const int lane = tid & 31;
    const int wid  = tid >> 5;
    const int warpM = wid >> 2;
    const int warpN = wid & 3;
    const int m0 = blockIdx.y * 128;
    const int n0 = n_base + blockIdx.x * 128;

    constexpr int CHUNKS = KB / BK;

    auto load_chunk = [&](int c, int stg) {
        const int kcol = c * BK;
        const uint32_t base = sbase + stg * G_STAGE;
        if (TERMS == 3) {
            #pragma unroll
            for (int it = 0; it < 8; it++) {
                int idx = tid + it * 256;
                int arr = idx >> 9;
                int j = idx & 511;
                int row = j >> 2, c16 = j & 3;
                const __half* src =
                    (arr == 0) ? Ahi + (size_t)(m0 + row) * KB + kcol + c16 * 8 :
                    (arr == 1) ? Alo + (size_t)(m0 + row) * KB + kcol + c16 * 8 :
                    (arr == 2) ? Bhi + (size_t)(n0 + row) * KB + kcol + c16 * 8 :
                                 Blo + (size_t)(n0 + row) * KB + kcol + c16 * 8;
                CP_ASYNC16(base + arr * G_AR + (row * ASTRIDE + c16 * 8) * 2, src);
            }
        } else {
            #pragma unroll
            for (int it = 0; it < 4; it++) {
                int idx = tid + it * 256;
                int half_ = idx >> 9;
                int j = idx & 511;
                int row = j >> 2, c16 = j & 3;
                const __half* src = half_
                    ? Bhi + (size_t)(n0 + row) * KB + kcol + c16 * 8
                    : Ahi + (size_t)(m0 + row) * KB + kcol + c16 * 8;
                CP_ASYNC16(base + (half_ ? 2 : 0) * G_AR + (row * ASTRIDE + c16 * 8) * 2, src);
            }
        }
        CP_COMMIT();
    };

    float    accF[4][4][4];
    uint32_t accA[4][4][2];
    uint32_t accB[4][4][2];
    #pragma unroll
    for (int i = 0; i < 4; i++)
        #pragma unroll
        for (int j = 0; j < 4; j++) {
            #pragma unroll
            for (int r = 0; r < 4; r++) accF[i][j][r] = 0.f;
            accA[i][j][0] = accA[i][j][1] = 0u;
            accB[i][j][0] = accB[i][j][1] = 0u;
        }

    #pragma unroll
    for (int s = 0; s < STAGES - 1; s++) load_chunk(s, s);

    for (int c = 0; c < CHUNKS; c++) {
        CP_WAIT(STAGES - 2);
        __syncthreads();

        const uint32_t base = sbase + (c % STAGES) * G_STAGE;
        const uint32_t ahB = base, alB = base + G_AR, bhB = base + 2 * G_AR, blB = base + 3 * G_AR;
        #pragma unroll
        for (int k0 = 0; k0 < BK; k0 += 16) {
            uint32_t ah[4][4], al[4][4];
            uint32_t colA = k0 + (lane >> 4) * 8;
            #pragma unroll
            for (int i = 0; i < 4; i++) {
                uint32_t roff = ((warpM * 64 + i * 16 + (lane & 15)) * ASTRIDE + colA) * 2;
                LDSM_X4(ah[i][0], ah[i][1], ah[i][2], ah[i][3], ahB + roff);
                if (TERMS == 3)
                    LDSM_X4(al[i][0], al[i][1], al[i][2], al[i][3], alB + roff);
            }
            uint32_t bh[2][4], bl[2][4];
            int g = lane >> 3, rr = lane & 7;
            #pragma unroll
            for (int j2 = 0; j2 < 2; j2++) {
                uint32_t roff = ((warpN * 32 + j2 * 16 + (g & 2) * 4 + rr) * ASTRIDE
                                 + k0 + (g & 1) * 8) * 2;
                LDSM_X4(bh[j2][0], bh[j2][1], bh[j2][2], bh[j2][3], bhB + roff);
                if (TERMS == 3)
                    LDSM_X4(bl[j2][0], bl[j2][1], bl[j2][2], bl[j2][3], blB + roff);
            }
            #pragma unroll
            for (int i = 0; i < 4; i++)
                #pragma unroll
                for (int j = 0; j < 4; j++) {
                    uint32_t b0h = bh[j >> 1][(j & 1) * 2], b1h = bh[j >> 1][(j & 1) * 2 + 1];
                    MMA16816F(accF[i][j], ah[i], b0h, b1h);
                    if (TERMS == 3) {
                        uint32_t b0l = bl[j >> 1][(j & 1) * 2], b1l = bl[j >> 1][(j & 1) * 2 + 1];
                        MMA16816H(accA[i][j], al[i], b0h, b1h);
                        MMA16816H(accB[i][j], ah[i], b0l, b1l);
                    }
                }
        }
        if (c + STAGES - 1 < CHUNKS) load_chunk(c + STAGES - 1, (c + STAGES - 1) % STAGES);
        else CP_COMMIT();
    }

    const float gamma = res ? *gammaP : 0.f;
    #pragma unroll
    for (int i = 0; i < 4; i++) {
        #pragma unroll
        for (int j = 0; j < 4; j++) {
            float t0 = accF[i][j][0], t1 = accF[i][j][1];
            float t2 = accF[i][j][2], t3 = accF[i][j][3];
            if (TERMS == 3) {
                float2 a01 = __half22float2(*(__half2*)&accA[i][j][0]);
                float2 a23 = __half22float2(*(__half2*)&accA[i][j][1]);
                float2 b01 = __half22float2(*(__half2*)&accB[i][j][0]);
                float2 b23 = __half22float2(*(__half2*)&accB[i][j][1]);
                t0 += a01.x + b01.x; t1 += a01.y + b01.y;
                t2 += a23.x + b23.x; t3 += a23.y + b23.y;
            }
            int gr = m0 + warpM * 64 + i * 16 + (lane >> 2);
            int gc = (n0 - n_base) + warpN * 32 + j * 8 + (lane & 3) * 2;
            size_t off0 = (size_t)gr * ldc + gc;
            size_t off1 = off0 + (size_t)8 * ldc;
            if (OUTH == 1) {
                *(__half2*)(Ch + off0) = __floats2half2_rn(t0, t1);
                *(__half2*)(Ch + off1) = __floats2half2_rn(t2, t3);
            } else if (res) {
                float2 r0 = *(const float2*)(res + off0);
                float2 r1 = *(const float2*)(res + off1);
                *(float2*)(C + off0) = make_float2(fmaf(gamma, t0, r0.x), fmaf(gamma, t1, r0.y));
                *(float2*)(C + off1) = make_float2(fmaf(gamma, t2, r1.x), fmaf(gamma, t3, r1.y));
            } else {
                *(float2*)(C + off0) = make_float2(t0, t1);
                *(float2*)(C + off1) = make_float2(t2, t3);
            }
        }
    }
}

// ---------------- 2x2 maxpool: phi (thph cols 64-127) -> fp16 hi/lo ----------------
__global__ void pool_phi_k(const float* __restrict__ thph,
                           __half* __restrict__ fhi, __half* __restrict__ flo)
{
    const int NPHI4 = BATCH * SEQ_K * (D_DIM / 4);
    int i = blockIdx.x * blockDim.x + threadIdx.x;
    if (i >= NPHI4) return;
    int bp = i >> 4, c4 = i & 15;
    int b = bp >> 10, ij = bp & 1023, ii = ij >> 5, jj = ij & 31;
    int r = b * 4096 + ii * 128 + jj * 2;
    const float* base = thph + 64 + (size_t)c4 * 4;
    float4 v0 = *(const float4*)(base + (size_t)r * 128);
    float4 v1 = *(const float4*)(base + (size_t)(r + 1) * 128);
    float4 v2 = *(const float4*)(base + (size_t)(r + 64) * 128);
    float4 v3 = *(const float4*)(base + (size_t)(r + 65) * 128);
    float f[4];
    f[0] = fmaxf(fmaxf(v0.x, v1.x), fmaxf(v2.x, v3.x));
    f[1] = fmaxf(fmaxf(v0.y, v1.y), fmaxf(v2.y, v3.y));
    f[2] = fmaxf(fmaxf(v0.z, v1.z), fmaxf(v2.z, v3.z));
    f[3] = fmaxf(fmaxf(v0.w, v1.w), fmaxf(v2.w, v3.w));
    __half h[4], l[4];
    #pragma unroll
    for (int j = 0; j < 4; j++) {
        h[j] = __float2half(f[j]);
        l[j] = __float2half(f[j] - __half2float(h[j]));
    }
    size_t off = (size_t)bp * 64 + c4 * 4;
    *(uint2*)(fhi + off) = *(const uint2*)h;
    *(uint2*)(flo + off) = *(const uint2*)l;
}

// ---------------- pool + transpose g: gh fp16 [M,256] -> gth [b][v][k] fp16 ----------
__global__ void transT_pool_g_k(const __half* __restrict__ gh,
                                __half* __restrict__ gth)
{
    __shared__ float sm[32][33];
    const int t = threadIdx.x;
    const int v0 = blockIdx.x * 32;
    const int k0 = blockIdx.y * 32;
    const int b  = blockIdx.z;
    {
        int r = t >> 3, cg = t & 7;
        int kk = k0 + r;
        int ii = kk >> 5, jj = kk & 31;
        size_t rbase = (size_t)(b * 4096 + ii * 128 + jj * 2) * V_DIM + v0 + cg * 4;
        uint2 u0 = *(const uint2*)(gh + rbase);
        uint2 u1 = *(const uint2*)(gh + rbase + V_DIM);
        uint2 u2 = *(const uint2*)(gh + rbase + (size_t)64 * V_DIM);
        uint2 u3 = *(const uint2*)(gh + rbase + (size_t)65 * V_DIM);
        float2 a0 = __half22float2(((const __half2*)&u0)[0]);
        float2 a1 = __half22float2(((const __half2*)&u0)[1]);
        float2 b0 = __half22float2(((const __half2*)&u1)[0]);
        float2 b1 = __half22float2(((const __half2*)&u1)[1]);
        float2 c0 = __half22float2(((const __half2*)&u2)[0]);
        float2 c1 = __half22float2(((const __half2*)&u2)[1]);
        float2 d0 = __half22float2(((const __half2*)&u3)[0]);
        float2 d1 = __half22float2(((const __half2*)&u3)[1]);
        sm[r][cg * 4 + 0] = fmaxf(fmaxf(a0.x, b0.x), fmaxf(c0.x, d0.x));
        sm[r][cg * 4 + 1] = fmaxf(fmaxf(a0.y, b0.y), fmaxf(c0.y, d0.y));
        sm[r][cg * 4 + 2] = fmaxf(fmaxf(a1.x, b1.x), fmaxf(c1.x, d1.x));
        sm[r][cg * 4 + 3] = fmaxf(fmaxf(a1.y, b1.y), fmaxf(c1.y, d1.y));
    }
    __syncthreads();
    {
        int v = t >> 3, kg = t & 7;
        __half h[4];
        #pragma unroll
        for (int j = 0; j < 4; j++)
            h[j] = __float2half(sm[kg * 4 + j][v]);
        size_t off = (size_t)(b * V_DIM + v0 + v) * SEQ_K + k0 + kg * 4;
        *(uint2*)(gth + off) = *(const uint2*)h;
    }
}

// ================= flash attention (fp16; P, g, tmp single-precision fp16) ===========
#define OFF_TH  0u
#define OFF_TL  9216u
#define OFF_FB(buf) (18432u + (buf) * 9216u)
#define OFF_GH  36864u
#define OFF_SP  55296u
#define ATTN_H_ELEMS 64512u
#define ATTN_SMEM_BYTES (64512 * 2 + 2 * 512 * 4)   // 133120

__global__ __launch_bounds__(512, 1) void attn_k(
    const float* __restrict__ thph,
    const __half* __restrict__ fhi, const __half* __restrict__ flo,
    const __half* __restrict__ gth,
    __half* __restrict__ thi)
{
    extern __shared__ __half sb[];
    float* redA = (float*)(sb + ATTN_H_ELEMS);
    float* redB = redA + 512;

    const uint32_t sb32 = smem_u32(sb);
    const int tid  = threadIdx.x;
    const int lane = tid & 31;
    const int wid  = tid >> 5;
    const int warpM = wid >> 2;
    const int warpN = wid & 3;
    const int b  = blockIdx.y;
    const int qt = blockIdx.x;
    const int qbase = b * SEQ_Q + qt * 128;
    const float L2E = 1.4426950408889634f;

    auto issue_phi = [&](int kt, int buf) {
        const size_t fb = (size_t)(b * SEQ_K + kt * 64) * 64;
        const uint32_t fB = OFF_FB(buf);
        #pragma unroll
        for (int i = 0; i < 2; i++) {
            int id = tid + i * 512;
            int half_ = id >> 9, j = id & 511;
            int row = j >> 3, c = j & 7;
            CP_ASYNC16(sb32 + (fB + half_ * 4608u + row * 72 + c * 8) * 2,
                       (half_ ? flo : fhi) + fb + (size_t)row * 64 + c * 8);
        }
        CP_COMMIT();
    };
    issue_phi(0, 0);

    // theta (thph cols 0-63, scaled by log2e) -> smem fp16 hi/lo
    #pragma unroll
    for (int i = tid; i < 128 * 16; i += 512) {
        int q = i >> 4, c4 = i & 15;
        float4 v = *(const float4*)(thph + (size_t)(qbase + q) * 128 + c4 * 4);
        float f[4] = {v.x * L2E, v.y * L2E, v.z * L2E, v.w * L2E};
        __half h[4], l[4];
        #pragma unroll
        for (int j = 0; j < 4; j++) {
            h[j] = __float2half(f[j]);
            l[j] = __float2half(f[j] - __half2float(h[j]));
        }
        uint32_t o = q * 72 + c4 * 4;
        *(uint2*)(sb + OFF_TH + o) = *(const uint2*)h;
        *(uint2*)(sb + OFF_TL + o) = *(const uint2*)l;
    }

    float acc[2][8][4];
    float m[2][2], l[2][2];
    #pragma unroll
    for (int mf = 0; mf < 2; mf++) {
        m[mf][0] = -1e30f; m[mf][1] = -1e30f;
        l[mf][0] = 0.f;    l[mf][1] = 0.f;
        #pragma unroll
        for (int nf = 0; nf < 8; nf++)
            #pragma unroll
            for (int c = 0; c < 4; c++) acc[mf][nf][c] = 0.f;
    }

    const int rowA = warpM * 32 + (lane & 15);
    const int rq   = lane >> 2;
    const int cq2  = (lane & 3) * 2;

    for (int kt = 0; kt < 16; kt++) {
        const int buf = kt & 1;
        __syncthreads();
        {
            const size_t gb = (size_t)b * V_DIM * SEQ_K + kt * 64;
            #pragma unroll
            for (int i = 0; i < 4; i++) {
                int id = tid + i * 512;
                int v = id >> 3, c = id & 7;
                CP_ASYNC16(sb32 + (OFF_GH + v * 72 + c * 8) * 2,
                           gth + gb + (size_t)v * SEQ_K + c * 8);
            }
            CP_COMMIT();
        }
        CP_WAIT(1);
        __syncthreads();

        const uint32_t fH = OFF_FB(buf), fL = fH + 4608u;
        float aq[2][2][4];
        #pragma unroll
        for (int mf = 0; mf < 2; mf++)
            #pragma unroll
            for (int nf = 0; nf < 2; nf++)
                #pragma unroll
                for (int c = 0; c < 4; c++) aq[mf][nf][c] = 0.f;

        #pragma unroll
        for (int k0 = 0; k0 < 64; k0 += 16) {
            uint32_t th0[4], th1[4], tl0[4], tl1[4], fh[4], fl[4];
            uint32_t colA = k0 + (lane >> 4) * 8;
            LDSM_X4(th0[0], th0[1], th0[2], th0[3], sb32 + (OFF_TH + (rowA) * 72 + colA) * 2);
            LDSM_X4(th1[0], th1[1], th1[2], th1[3], sb32 + (OFF_TH + (rowA + 16) * 72 + colA) * 2);
            LDSM_X4(tl0[0], tl0[1], tl0[2], tl0[3], sb32 + (OFF_TL + (rowA) * 72 + colA) * 2);
            LDSM_X4(tl1[0], tl1[1], tl1[2], tl1[3], sb32 + (OFF_TL + (rowA + 16) * 72 + colA) * 2);
            int g = lane >> 3, rr = lane & 7;
            uint32_t brow = (warpN * 16 + (g & 2) * 4 + rr) * 72 + k0 + (g & 1) * 8;
            LDSM_X4(fh[0], fh[1], fh[2], fh[3], sb32 + (fH + brow) * 2);
            LDSM_X4(fl[0], fl[1], fl[2], fl[3], sb32 + (fL + brow) * 2);
            MMA16816F(aq[0][0], th0, fh[0], fh[1]);
            MMA16816F(aq[0][1], th0, fh[2], fh[3]);
            MMA16816F(aq[1][0], th1, fh[0], fh[1]);
            MMA16816F(aq[1][1], th1, fh[2], fh[3]);
            MMA16816F(aq[0][0], tl0, fh[0], fh[1]);
            MMA16816F(aq[0][1], tl0, fh[2], fh[3]);
            MMA16816F(aq[1][0], tl1, fh[0], fh[1]);
            MMA16816F(aq[1][1], tl1, fh[2], fh[3]);
            MMA16816F(aq[0][0], th0, fl[0], fl[1]);
            MMA16816F(aq[0][1], th0, fl[2], fl[3]);
            MMA16816F(aq[1][0], th1, fl[0], fl[1]);
            MMA16816F(aq[1][1], th1, fl[2], fl[3]);
        }

        if (kt + 1 < 16) issue_phi(kt + 1, buf ^ 1);

        float mx[2][2];
        #pragma unroll
        for (int mf = 0; mf < 2; mf++)
            #pragma unroll
            for (int h = 0; h < 2; h++) {
                float t = fmaxf(fmaxf(aq[mf][0][h * 2], aq[mf][0][h * 2 + 1]),
                                fmaxf(aq[mf][1][h * 2], aq[mf][1][h * 2 + 1]));
                t = fmaxf(t, __shfl_xor_sync(0xffffffffu, t, 1));
                t = fmaxf(t, __shfl_xor_sync(0xffffffffu, t, 2));
                mx[mf][h] = t;
            }
        if ((lane & 3) == 0) {
            #pragma unroll
            for (int mf = 0; mf < 2; mf++)
                #pragma unroll
                for (int h = 0; h < 2; h++)
                    redA[warpN * 128 + warpM * 32 + mf * 16 + h * 8 + rq] = mx[mf][h];
        }
        __syncthreads();

        float mnew[2][2], scale[2][2], rsum[2][2];
        #pragma unroll
        for (int mf = 0; mf < 2; mf++)
            #pragma unroll
            for (int h = 0; h < 2; h++) {
                int r = warpM * 32 + mf * 16 + h * 8 + rq;
                float v = m[mf][h];
                #pragma unroll
                for (int w = 0; w < 4; w++) v = fmaxf(v, redA[w * 128 + r]);
                mnew[mf][h] = v;
                rsum[mf][h] = 0.f;
            }

        #pragma unroll
        for (int mf = 0; mf < 2; mf++)
            #pragma unroll
            for (int nf = 0; nf < 2; nf++)
                #pragma unroll
                for (int h = 0; h < 2; h++) {
                    float p0 = ex2f(aq[mf][nf][h * 2]     - mnew[mf][h]);
                    float p1 = ex2f(aq[mf][nf][h * 2 + 1] - mnew[mf][h]);
                    rsum[mf][h] += p0 + p1;
                    int row = warpM * 32 + mf * 16 + h * 8 + rq;
                    int col = warpN * 16 + nf * 8 + cq2;
                    *(__half2*)(sb + OFF_SP + row * 72 + col) = __floats2half2_rn(p0, p1);
                }
        #pragma unroll
        for (int mf = 0; mf < 2; mf++)
            #pragma unroll
            for (int h = 0; h < 2; h++) {
                float t = rsum[mf][h];
                t += __shfl_xor_sync(0xffffffffu, t, 1);
                t += __shfl_xor_sync(0xffffffffu, t, 2);
                rsum[mf][h] = t;
                scale[mf][h] = ex2f(m[mf][h] - mnew[mf][h]);
                m[mf][h] = mnew[mf][h];
            }
        if ((lane & 3) == 0) {
            #pragma unroll
            for (int mf = 0; mf < 2; mf++)
                #pragma unroll
                for (int h = 0; h < 2; h++)
                    redB[warpN * 128 + warpM * 32 + mf * 16 + h * 8 + rq] = rsum[mf][h];
        }
        if (kt + 1 < 16) { CP_WAIT(1); }
        else             { CP_WAIT(0); }
        __syncthreads();

        #pragma unroll
        for (int mf = 0; mf < 2; mf++)
            #pragma unroll
            for (int h = 0; h < 2; h++) {
                int r = warpM * 32 + mf * 16 + h * 8 + rq;
                float s = 0.f;
                #pragma unroll
                for (int w = 0; w < 4; w++) s += redB[w * 128 + r];
                l[mf][h] = l[mf][h] * scale[mf][h] + s;
            }
        #pragma unroll
        for (int mf = 0; mf < 2; mf++)
            #pragma unroll
            for (int nf = 0; nf < 8; nf++) {
                acc[mf][nf][0] *= scale[mf][0];
                acc[mf][nf][1] *= scale[mf][0];
                acc[mf][nf][2] *= scale[mf][1];
                acc[mf][nf][3] *= scale[mf][1];
            }

        #pragma unroll
        for (int k0 = 0; k0 < 64; k0 += 16) {
            uint32_t ph0[4], ph1[4];
            uint32_t colA = k0 + (lane >> 4) * 8;
            LDSM_X4(ph0[0], ph0[1], ph0[2], ph0[3], sb32 + (OFF_SP + (rowA) * 72 + colA) * 2);
            LDSM_X4(ph1[0], ph1[1], ph1[2], ph1[3], sb32 + (OFF_SP + (rowA + 16) * 72 + colA) * 2);
            int g = lane >> 3, rr = lane & 7;
            #pragma unroll
            for (int j2 = 0; j2 < 4; j2++) {
                uint32_t gh4[4];
                uint32_t brow = (warpN * 64 + j2 * 16 + (g & 2) * 4 + rr) * 72 + k0 + (g & 1) * 8;
                LDSM_X4(gh4[0], gh4[1], gh4[2], gh4[3], sb32 + (OFF_GH + brow) * 2);
                MMA16816F(acc[0][j2 * 2 + 0], ph0, gh4[0], gh4[1]);
                MMA16816F(acc[0][j2 * 2 + 1], ph0, gh4[2], gh4[3]);
                MMA16816F(acc[1][j2 * 2 + 0], ph1, gh4[0], gh4[1]);
                MMA16816F(acc[1][j2 * 2 + 1], ph1, gh4[2], gh4[3]);
            }
        }
    }

    #pragma unroll
    for (int mf = 0; mf < 2; mf++)
        #pragma unroll
        for (int h = 0; h < 2; h++) {
            float inv = 1.f / l[mf][h];
            int row = qbase + warpM * 32 + mf * 16 + h * 8 + rq;
            #pragma unroll
            for (int nf = 0; nf < 8; nf++) {
                int col = warpN * 64 + nf * 8 + cq2;
                float v0 = acc[mf][nf][h * 2]     * inv;
                float v1 = acc[mf][nf][h * 2 + 1] * inv;
                *(__half2*)(thi + (size_t)row * V_DIM + col) = __floats2half2_rn(v0, v1);
            }
        }
}

// ---------------- launch ----------------
extern "C" void kernel_launch(void* const* d_in, const int* in_sizes, int n_in,
                              void* d_out, int out_size)
{
    const float* x     = (const float*)d_in[0];
    const float* Wt    = (const float*)d_in[1];
    const float* Wp    = (const float*)d_in[2];
    const float* Wg    = (const float*)d_in[3];
    const float* Wo    = (const float*)d_in[4];
    const float* gamma = (const float*)d_in[5];
    float* out = (float*)d_out;

    float *thph;
    __half *gh, *xhi, *xlo, *thi, *Bph, *Bpl, *Boh, *fhi, *flo, *gth;
    cudaGetSymbolAddress((void**)&thph, g_thph);
    cudaGetSymbolAddress((void**)&gh,   g_gh);
    cudaGetSymbolAddress((void**)&xhi,  g_xhi);
    cudaGetSymbolAddress((void**)&xlo,  g_xlo);
    cudaGetSymbolAddress((void**)&thi,  g_thi);
    cudaGetSymbolAddress((void**)&Bph,  g_Bp_hi);
    cudaGetSymbolAddress((void**)&Bpl,  g_Bp_lo);
    cudaGetSymbolAddress((void**)&Boh,  g_Bo_hi);
    cudaGetSymbolAddress((void**)&fhi,  g_fhi);
    cudaGetSymbolAddress((void**)&flo,  g_flo);
    cudaGetSymbolAddress((void**)&gth,  g_gth);

    cudaFuncSetAttribute((const void*)gemm_mma<512, 3, 0>, cudaFuncAttributeMaxDynamicSharedMemorySize, GEMM_SMEM_BYTES);
    cudaFuncSetAttribute((const void*)gemm_mma<512, 1, 1>, cudaFuncAttributeMaxDynamicSharedMemorySize, GEMM_SMEM_BYTES);
    cudaFuncSetAttribute((const void*)gemm_mma<256, 1, 0>, cudaFuncAttributeMaxDynamicSharedMemorySize, GEMM_SMEM_BYTES);
    cudaFuncSetAttribute(attn_k, cudaFuncAttributeMaxDynamicSharedMemorySize, ATTN_SMEM_BYTES);

    convert_x_k<<<(M_ROWS * C_IN / 8 + 255) / 256, 256>>>(x, xhi, xlo);
    pack_proj_k<<<(NPROJ * C_IN + 255) / 256, 256>>>(Wt, Wp, Wg, Bph, Bpl);
    pack_wo_k<<<(C_IN * V_DIM + 255) / 256, 256>>>(Wo, Boh);
    // theta|phi: 3-term split precision -> compact fp32 [M,128]
    gemm_mma<512, 3, 0><<<dim3(1, M_ROWS / 128), 256, GEMM_SMEM_BYTES>>>(
        xhi, xlo, Bph, Bpl, thph, nullptr, 128, 0, nullptr, nullptr);
    // g: 1-term -> fp16 [M,256] directly
    gemm_mma<512, 1, 1><<<dim3(2, M_ROWS / 128), 256, GEMM_SMEM_BYTES>>>(
        xhi, nullptr, Bph, nullptr, nullptr, gh, 256, 128, nullptr, nullptr);
    pool_phi_k<<<(BATCH * SEQ_K * (D_DIM / 4) + 255) / 256, 256>>>(thph, fhi, flo);
    transT_pool_g_k<<<dim3(V_DIM / 32, SEQ_K / 32, BATCH), 256>>>(gh, gth);
    attn_k<<<dim3(SEQ_Q / 128, BATCH), 512, ATTN_SMEM_BYTES>>>(
        thph, fhi, flo, gth, thi);
    // Wo projection (1-term) + residual: out = gamma * (tmp @ Wo) + x
    gemm_mma<256, 1, 0><<<dim3(C_IN / 128, M_ROWS / 128), 256, GEMM_SMEM_BYTES>>>(
        thi, nullptr, Boh, nullptr, out, nullptr, C_IN, 0, x, gamma);
}